// round 1
// baseline (speedup 1.0000x reference)
#include <cuda_runtime.h>

// ViT_15358803051012 — fused forward, fp32, warp-per-element.
// Layout per warp in dynamic smem (floats):
//   P[784]  patches -> tok2 -> tok3 (reused)
//   Q[784]  Q1 -> Q2
//   K[784]  K1 -> K2
//   V[784]  V1 -> V2
//   S[256]  attention score matrix (16x16 then 8x8)
//   H[32]   fc1 hidden
#define WSM 3424
#define WARPS_PER_BLOCK 2

// Packed layer-1 weights (low half, i<16) and pos-emb-folded biases.
__device__ float d_W1[3 * 49 * 256];   // [m][s][o][i]
__device__ float d_B1[3 * 49 * 16];    // [m][s][o]

__global__ void prep_kernel(const float* __restrict__ pos_emb,
                            const float* __restrict__ WQ1,
                            const float* __restrict__ WK1,
                            const float* __restrict__ WV1) {
    int t = blockIdx.x * blockDim.x + threadIdx.x;   // over 3*49*16 = 2352
    if (t >= 3 * 49 * 16) return;
    int m = t / 784;
    int r = t - m * 784;
    int s = r >> 4;
    int o = r & 15;
    const float* W = (m == 0) ? WQ1 : (m == 1) ? WK1 : WV1;
    const float* wrow = W + (s * 16 + o) * 32;
    const float* pe = pos_emb + s * 16;            // pos_emb (7,7,16) == (49,16)
    float* dst = d_W1 + (m * 49 + s) * 256 + o * 16;
    float bias = 0.f;
#pragma unroll
    for (int i = 0; i < 16; i++) {
        dst[i] = wrow[i];
        bias = fmaf(pe[i], wrow[16 + i], bias);
    }
    d_B1[(m * 49 + s) * 16 + o] = bias;
}

__device__ __forceinline__ float dot16(const float* a, const float4* __restrict__ w4, float acc) {
    float4 w0 = w4[0], w1 = w4[1], w2 = w4[2], w3 = w4[3];
    acc = fmaf(a[0],  w0.x, acc); acc = fmaf(a[1],  w0.y, acc);
    acc = fmaf(a[2],  w0.z, acc); acc = fmaf(a[3],  w0.w, acc);
    acc = fmaf(a[4],  w1.x, acc); acc = fmaf(a[5],  w1.y, acc);
    acc = fmaf(a[6],  w1.z, acc); acc = fmaf(a[7],  w1.w, acc);
    acc = fmaf(a[8],  w2.x, acc); acc = fmaf(a[9],  w2.y, acc);
    acc = fmaf(a[10], w2.z, acc); acc = fmaf(a[11], w2.w, acc);
    acc = fmaf(a[12], w3.x, acc); acc = fmaf(a[13], w3.y, acc);
    acc = fmaf(a[14], w3.z, acc); acc = fmaf(a[15], w3.w, acc);
    return acc;
}

__global__ __launch_bounds__(WARPS_PER_BLOCK * 32) void vit_kernel(
    const float* __restrict__ x,
    const float* __restrict__ W2q,
    const float* __restrict__ W2k,
    const float* __restrict__ W2v,
    const float* __restrict__ fc1w,
    const float* __restrict__ fc1b,
    const float* __restrict__ fc2w,
    const float* __restrict__ fc2b,
    float* __restrict__ out)
{
    extern __shared__ float smem[];
    const int warp = threadIdx.x >> 5;
    const int ln   = threadIdx.x & 31;
    const int b    = blockIdx.x * WARPS_PER_BLOCK + warp;

    float* P = smem + warp * WSM;
    float* Q = P + 784;
    float* K = Q + 784;
    float* V = K + 784;
    float* S = V + 784;
    float* H = S + 256;

    // ---- stage 0: grayscale + patchify (float4 everywhere) ----
    const float4* x4 = (const float4*)(x + (size_t)b * 2352);
    for (int j = ln; j < 196; j += 32) {
        float4 rc = x4[j];
        float4 gc = x4[196 + j];
        float4 bc = x4[392 + j];
        float4 g;
        g.x = 0.299f * rc.x + 0.587f * gc.x + 0.114f * bc.x;
        g.y = 0.299f * rc.y + 0.587f * gc.y + 0.114f * bc.y;
        g.z = 0.299f * rc.z + 0.587f * gc.z + 0.114f * bc.z;
        g.w = 0.299f * rc.w + 0.587f * gc.w + 0.114f * bc.w;
        int row = j / 7;
        int pc  = j - row * 7;
        int p   = (row >> 2) * 7 + pc;
        int i   = (row & 3) << 2;
        *(float4*)&P[p * 16 + i] = g;
    }
    __syncwarp();

    // ---- stage A: layer-1 projections Q1/K1/V1 (49x16 each), bias = folded pos_emb ----
    for (int t = ln; t < 147; t += 32) {
        int s = t / 3;
        int m = t - s * 3;
        float a[16];
        const float4* pr = (const float4*)&P[s * 16];
        ((float4*)a)[0] = pr[0];
        ((float4*)a)[1] = pr[1];
        ((float4*)a)[2] = pr[2];
        ((float4*)a)[3] = pr[3];
        const float4* w4 = (const float4*)(d_W1 + (m * 49 + s) * 256);
        const float*  bs = d_B1 + (m * 49 + s) * 16;
        float* dst = ((m == 0) ? Q : (m == 1) ? K : V) + s * 16;
#pragma unroll
        for (int o = 0; o < 16; o++) {
            dst[o] = dot16(a, w4 + o * 4, bs[o]);
        }
    }
    __syncwarp();

    // ---- stage B1: S[d][e] = (1/7) * sum_s Q1[s,d]*K1[s,e]  (16x16) ----
    {
        int e  = ln & 15;
        int dg = ln >> 4;                  // lane owns 8 d's: dg*8 .. dg*8+7
        float acc[8];
#pragma unroll
        for (int d = 0; d < 8; d++) acc[d] = 0.f;
        for (int s = 0; s < 49; s++) {
            float kv = K[s * 16 + e];
            float4 q0 = *(const float4*)&Q[s * 16 + dg * 8];
            float4 q1 = *(const float4*)&Q[s * 16 + dg * 8 + 4];
            acc[0] = fmaf(q0.x, kv, acc[0]);
            acc[1] = fmaf(q0.y, kv, acc[1]);
            acc[2] = fmaf(q0.z, kv, acc[2]);
            acc[3] = fmaf(q0.w, kv, acc[3]);
            acc[4] = fmaf(q1.x, kv, acc[4]);
            acc[5] = fmaf(q1.y, kv, acc[5]);
            acc[6] = fmaf(q1.z, kv, acc[6]);
            acc[7] = fmaf(q1.w, kv, acc[7]);
        }
        const float sc = 1.0f / 7.0f;
#pragma unroll
        for (int d = 0; d < 8; d++) S[(dg * 8 + d) * 16 + e] = acc[d] * sc;
    }
    __syncwarp();

    // ---- stage B2: tok2[s,d] = softmax_d( sum_e S[d,e]*V1[s,e] ), softmax fused via shfl ----
    {
        int d  = ln & 15;
        int sg = ln >> 4;
        unsigned gmask = 0xFFFFu << (sg * 16);
        float4 s0 = *(const float4*)&S[d * 16 + 0];
        float4 s1 = *(const float4*)&S[d * 16 + 4];
        float4 s2 = *(const float4*)&S[d * 16 + 8];
        float4 s3 = *(const float4*)&S[d * 16 + 12];
        for (int s = sg; s < 49; s += 2) {
            float4 v0 = *(const float4*)&V[s * 16 + 0];
            float4 v1 = *(const float4*)&V[s * 16 + 4];
            float4 v2 = *(const float4*)&V[s * 16 + 8];
            float4 v3 = *(const float4*)&V[s * 16 + 12];
            float a0 = s0.x * v0.x, a1 = s0.y * v0.y;
            a0 = fmaf(s0.z, v0.z, a0); a1 = fmaf(s0.w, v0.w, a1);
            a0 = fmaf(s1.x, v1.x, a0); a1 = fmaf(s1.y, v1.y, a1);
            a0 = fmaf(s1.z, v1.z, a0); a1 = fmaf(s1.w, v1.w, a1);
            a0 = fmaf(s2.x, v2.x, a0); a1 = fmaf(s2.y, v2.y, a1);
            a0 = fmaf(s2.z, v2.z, a0); a1 = fmaf(s2.w, v2.w, a1);
            a0 = fmaf(s3.x, v3.x, a0); a1 = fmaf(s3.y, v3.y, a1);
            a0 = fmaf(s3.z, v3.z, a0); a1 = fmaf(s3.w, v3.w, a1);
            float acc = a0 + a1;
            float mx = acc;
            mx = fmaxf(mx, __shfl_xor_sync(gmask, mx, 8));
            mx = fmaxf(mx, __shfl_xor_sync(gmask, mx, 4));
            mx = fmaxf(mx, __shfl_xor_sync(gmask, mx, 2));
            mx = fmaxf(mx, __shfl_xor_sync(gmask, mx, 1));
            float ex = __expf(acc - mx);
            float sum = ex;
            sum += __shfl_xor_sync(gmask, sum, 8);
            sum += __shfl_xor_sync(gmask, sum, 4);
            sum += __shfl_xor_sync(gmask, sum, 2);
            sum += __shfl_xor_sync(gmask, sum, 1);
            P[s * 16 + d] = ex / sum;
        }
    }
    __syncwarp();

    // ---- stage C: layer-2 projections Q2/K2/V2 (49x8 each) from tok2 in P ----
    for (int t = ln; t < 147; t += 32) {
        int s = t / 3;
        int m = t - s * 3;
        float a[16];
        const float4* pr = (const float4*)&P[s * 16];
        ((float4*)a)[0] = pr[0];
        ((float4*)a)[1] = pr[1];
        ((float4*)a)[2] = pr[2];
        ((float4*)a)[3] = pr[3];
        const float* Wm = (m == 0) ? W2q : (m == 1) ? W2k : W2v;
        const float4* w4 = (const float4*)(Wm + s * 128);   // (49,8,16)
        float* dst = ((m == 0) ? Q : (m == 1) ? K : V) + s * 8;
#pragma unroll
        for (int o = 0; o < 8; o++) {
            dst[o] = dot16(a, w4 + o * 4, 0.f);
        }
    }
    __syncwarp();

    // ---- stage D1: S2[d][e] (8x8) ----
    for (int idx = ln; idx < 64; idx += 32) {
        int d = idx >> 3, e = idx & 7;
        float acc = 0.f;
        for (int s = 0; s < 49; s++) acc = fmaf(Q[s * 8 + d], K[s * 8 + e], acc);
        S[idx] = acc * (1.0f / 7.0f);
    }
    __syncwarp();

    // ---- stage D2: tok3[s,d] = softmax_d( sum_e S2[d,e]*V2[s,e] ), fused softmax(8) ----
    {
        int d  = ln & 7;
        int sg = ln >> 3;                  // 4 groups of 8 lanes
        unsigned gmask = 0xFFu << (sg * 8);
        float4 s0 = *(const float4*)&S[d * 8];
        float4 s1 = *(const float4*)&S[d * 8 + 4];
        for (int s = sg; s < 49; s += 4) {
            float4 v0 = *(const float4*)&V[s * 8];
            float4 v1 = *(const float4*)&V[s * 8 + 4];
            float a0 = s0.x * v0.x, a1 = s0.y * v0.y;
            a0 = fmaf(s0.z, v0.z, a0); a1 = fmaf(s0.w, v0.w, a1);
            a0 = fmaf(s1.x, v1.x, a0); a1 = fmaf(s1.y, v1.y, a1);
            a0 = fmaf(s1.z, v1.z, a0); a1 = fmaf(s1.w, v1.w, a1);
            float acc = a0 + a1;
            float mx = acc;
            mx = fmaxf(mx, __shfl_xor_sync(gmask, mx, 4));
            mx = fmaxf(mx, __shfl_xor_sync(gmask, mx, 2));
            mx = fmaxf(mx, __shfl_xor_sync(gmask, mx, 1));
            float ex = __expf(acc - mx);
            float sum = ex;
            sum += __shfl_xor_sync(gmask, sum, 4);
            sum += __shfl_xor_sync(gmask, sum, 2);
            sum += __shfl_xor_sync(gmask, sum, 1);
            P[s * 8 + d] = ex / sum;       // tok3 (49x8) — tok2 is dead
        }
    }
    __syncwarp();

    // ---- stage E: fc1 (392 -> 16) + relu, 2 lanes per output ----
    {
        int o  = ln >> 1;
        int hh = ln & 1;
        const float4* w4 = (const float4*)(fc1w + o * 392) + hh * 49;
        const float4* f4 = (const float4*)P + hh * 49;
        float a0 = 0.f, a1 = 0.f, a2 = 0.f, a3 = 0.f;
        for (int k = 0; k < 49; k++) {
            float4 w = w4[k];
            float4 f = f4[k];
            a0 = fmaf(w.x, f.x, a0);
            a1 = fmaf(w.y, f.y, a1);
            a2 = fmaf(w.z, f.z, a2);
            a3 = fmaf(w.w, f.w, a3);
        }
        float acc = (a0 + a1) + (a2 + a3);
        acc += __shfl_xor_sync(0xFFFFFFFFu, acc, 1);
        if (hh == 0) H[o] = fmaxf(acc + fc1b[o], 0.f);
    }
    __syncwarp();

    // ---- fc2 (16 -> 10) + softmax(10) ----
    {
        float logit = -1e30f;
        if (ln < 10) {
            const float* w = fc2w + ln * 16;
            float acc = fc2b[ln];
#pragma unroll
            for (int i = 0; i < 16; i++) acc = fmaf(w[i], H[i], acc);
            logit = acc;
        }
        float mx = logit;
#pragma unroll
        for (int off = 16; off >= 1; off >>= 1)
            mx = fmaxf(mx, __shfl_xor_sync(0xFFFFFFFFu, mx, off));
        float ex = (ln < 10) ? __expf(logit - mx) : 0.f;
        float sum = ex;
#pragma unroll
        for (int off = 16; off >= 1; off >>= 1)
            sum += __shfl_xor_sync(0xFFFFFFFFu, sum, off);
        if (ln < 10) out[(size_t)b * 10 + ln] = ex / sum;
    }
}

extern "C" void kernel_launch(void* const* d_in, const int* in_sizes, int n_in,
                              void* d_out, int out_size) {
    const float* x    = (const float*)d_in[0];
    const float* pos  = (const float*)d_in[1];
    const float* WQ1  = (const float*)d_in[2];
    const float* WK1  = (const float*)d_in[3];
    const float* WV1  = (const float*)d_in[4];
    const float* WQ2  = (const float*)d_in[5];
    const float* WK2  = (const float*)d_in[6];
    const float* WV2  = (const float*)d_in[7];
    const float* fc1w = (const float*)d_in[8];
    const float* fc1b = (const float*)d_in[9];
    const float* fc2w = (const float*)d_in[10];
    const float* fc2b = (const float*)d_in[11];
    float* out = (float*)d_out;

    prep_kernel<<<10, 256>>>(pos, WQ1, WK1, WV1);

    const int warps = WARPS_PER_BLOCK;
    const int smem_bytes = WSM * warps * (int)sizeof(float);   // 27392 B < 48 KB
    vit_kernel<<<16384 / warps, warps * 32, smem_bytes>>>(
        x, WQ2, WK2, WV2, fc1w, fc1b, fc2w, fc2b, out);
}

// round 2
// speedup vs baseline: 2.8476x; 2.8476x over previous
#include <cuda_runtime.h>

// ViT_15358803051012 — block = 8 elements (8 warps). Projection stages (A/C)
// are element-blocked: each warp instruction computes 4 dots x 8 elements with
// weights broadcast across elements. Attention/softmax stages are warp-per-element.
//
// Per-element shared layout (WSM floats, padded for bank-conflict-free 8-elem stride):
//   [0..784)      P: patches -> tok2 -> tok3
//   [784..3136)   QKV layer1 (784 each); reused as QKV layer2 (392 each at +784,+1176,+1568)
//   [3136..3392)  S score matrix
//   [3392..3408)  H fc1 hidden
#define WSM 3428
#define ELEMS 8

__device__ float d_W1[2352 * 16];   // [t][i], t = s*48 + m*16 + o
__device__ float d_B1[2352];        // folded pos-emb bias
__device__ float d_W2[1176 * 16];   // [t][i], t = s*24 + m*8 + o
__device__ float d_FC1[6272];       // [(jc*16+o)*4 + j4]

__global__ void prep_kernel(const float* __restrict__ pos_emb,
                            const float* __restrict__ WQ1,
                            const float* __restrict__ WK1,
                            const float* __restrict__ WV1,
                            const float* __restrict__ WQ2,
                            const float* __restrict__ WK2,
                            const float* __restrict__ WV2,
                            const float* __restrict__ fc1w) {
    int t = blockIdx.x * blockDim.x + threadIdx.x;
    if (t < 2352) {
        int s = t / 48;
        int rem = t - s * 48;
        int m = rem >> 4;
        int o = rem & 15;
        const float* W = (m == 0) ? WQ1 : (m == 1) ? WK1 : WV1;
        const float* wrow = W + (s * 16 + o) * 32;
        const float* pe = pos_emb + s * 16;
        float bias = 0.f;
#pragma unroll
        for (int i = 0; i < 16; i++) {
            d_W1[t * 16 + i] = wrow[i];
            bias = fmaf(pe[i], wrow[16 + i], bias);
        }
        d_B1[t] = bias;
    } else if (t < 2352 + 1176) {
        int u = t - 2352;
        int s = u / 24;
        int rem = u - s * 24;
        int m = rem >> 3;
        int o = rem & 7;
        const float* W = (m == 0) ? WQ2 : (m == 1) ? WK2 : WV2;
        const float* wrow = W + (s * 8 + o) * 16;
#pragma unroll
        for (int i = 0; i < 16; i++) d_W2[u * 16 + i] = wrow[i];
    } else if (t < 2352 + 1176 + 6272) {
        int u = t - 3528;
        int jc = u >> 6;
        int rem = u & 63;
        int o = rem >> 2;
        int j4 = rem & 3;
        d_FC1[u] = fc1w[o * 392 + jc * 4 + j4];
    }
}

__device__ __forceinline__ float dot16(const float* a, const float4* __restrict__ w4, float acc) {
    float4 w0 = w4[0], w1 = w4[1], w2 = w4[2], w3 = w4[3];
    acc = fmaf(a[0],  w0.x, acc); acc = fmaf(a[1],  w0.y, acc);
    acc = fmaf(a[2],  w0.z, acc); acc = fmaf(a[3],  w0.w, acc);
    acc = fmaf(a[4],  w1.x, acc); acc = fmaf(a[5],  w1.y, acc);
    acc = fmaf(a[6],  w1.z, acc); acc = fmaf(a[7],  w1.w, acc);
    acc = fmaf(a[8],  w2.x, acc); acc = fmaf(a[9],  w2.y, acc);
    acc = fmaf(a[10], w2.z, acc); acc = fmaf(a[11], w2.w, acc);
    acc = fmaf(a[12], w3.x, acc); acc = fmaf(a[13], w3.y, acc);
    acc = fmaf(a[14], w3.z, acc); acc = fmaf(a[15], w3.w, acc);
    return acc;
}

__global__ __launch_bounds__(ELEMS * 32) void vit_kernel(
    const float* __restrict__ x,
    const float* __restrict__ fc1b,
    const float* __restrict__ fc2w,
    const float* __restrict__ fc2b,
    float* __restrict__ out)
{
    extern __shared__ float smem[];
    const int tid = threadIdx.x;
    const int w   = tid >> 5;
    const int ln  = tid & 31;
    const int bElem = blockIdx.x * ELEMS;

    float* Pw = smem + w * WSM;

    // ---- stage 0: warp w patchifies its own element ----
    {
        const float4* x4 = (const float4*)(x + (size_t)(bElem + w) * 2352);
        for (int j = ln; j < 196; j += 32) {
            float4 rc = x4[j];
            float4 gc = x4[196 + j];
            float4 bc = x4[392 + j];
            float4 g;
            g.x = 0.299f * rc.x + 0.587f * gc.x + 0.114f * bc.x;
            g.y = 0.299f * rc.y + 0.587f * gc.y + 0.114f * bc.y;
            g.z = 0.299f * rc.z + 0.587f * gc.z + 0.114f * bc.z;
            g.w = 0.299f * rc.w + 0.587f * gc.w + 0.114f * bc.w;
            int row = j / 7;
            int pc  = j - row * 7;
            int p   = (row >> 2) * 7 + pc;
            int i   = (row & 3) << 2;
            *(float4*)&Pw[p * 16 + i] = g;
        }
    }
    __syncthreads();

    // ---- stage A: layer-1 projections, element-blocked ----
    // lane = (e, oq): e = element 0..7, oq = output-quad slot 0..3
    // warp iteration processes dot-quad qb: t = qb*4 + oq, broadcast over 8 elements.
    {
        int e  = ln & 7;
        int oq = ln >> 3;
        float* Pe = smem + e * WSM;
        for (int qb = w; qb < 588; qb += ELEMS) {
            int t = qb * 4 + oq;
            int s = t / 48;
            int rem = t - s * 48;
            int m = rem >> 4;
            int o = rem & 15;
            float a[16];
            const float4* pr = (const float4*)(Pe + s * 16);
            ((float4*)a)[0] = pr[0];
            ((float4*)a)[1] = pr[1];
            ((float4*)a)[2] = pr[2];
            ((float4*)a)[3] = pr[3];
            const float4* w4 = (const float4*)(d_W1 + t * 16);
            float acc = dot16(a, w4, d_B1[t]);
            Pe[784 + m * 784 + s * 16 + o] = acc;
        }
    }
    __syncthreads();

    // ---- stage B1: S[d][e] = (1/7) sum_s Q1[s,d]*K1[s,e] (16x16), warp=element ----
    {
        float* Q = Pw + 784;
        float* K = Pw + 1568;
        float* S = Pw + 3136;
        int e  = ln & 15;
        int dg = ln >> 4;
        float acc[8];
#pragma unroll
        for (int d = 0; d < 8; d++) acc[d] = 0.f;
        for (int s = 0; s < 49; s++) {
            float kv = K[s * 16 + e];
            float4 q0 = *(const float4*)&Q[s * 16 + dg * 8];
            float4 q1 = *(const float4*)&Q[s * 16 + dg * 8 + 4];
            acc[0] = fmaf(q0.x, kv, acc[0]);
            acc[1] = fmaf(q0.y, kv, acc[1]);
            acc[2] = fmaf(q0.z, kv, acc[2]);
            acc[3] = fmaf(q0.w, kv, acc[3]);
            acc[4] = fmaf(q1.x, kv, acc[4]);
            acc[5] = fmaf(q1.y, kv, acc[5]);
            acc[6] = fmaf(q1.z, kv, acc[6]);
            acc[7] = fmaf(q1.w, kv, acc[7]);
        }
        const float sc = 1.0f / 7.0f;
#pragma unroll
        for (int d = 0; d < 8; d++) S[(dg * 8 + d) * 16 + e] = acc[d] * sc;
    }
    __syncwarp();

    // ---- stage B2: tok2[s,d] = softmax_d(sum_e S[d,e]*V1[s,e]) fused via shfl ----
    {
        float* V = Pw + 2352;
        float* S = Pw + 3136;
        int d  = ln & 15;
        int sg = ln >> 4;
        unsigned gmask = 0xFFFFu << (sg * 16);
        float4 s0 = *(const float4*)&S[d * 16 + 0];
        float4 s1 = *(const float4*)&S[d * 16 + 4];
        float4 s2 = *(const float4*)&S[d * 16 + 8];
        float4 s3 = *(const float4*)&S[d * 16 + 12];
        for (int s = sg; s < 49; s += 2) {
            float4 v0 = *(const float4*)&V[s * 16 + 0];
            float4 v1 = *(const float4*)&V[s * 16 + 4];
            float4 v2 = *(const float4*)&V[s * 16 + 8];
            float4 v3 = *(const float4*)&V[s * 16 + 12];
            float a0 = s0.x * v0.x, a1 = s0.y * v0.y;
            a0 = fmaf(s0.z, v0.z, a0); a1 = fmaf(s0.w, v0.w, a1);
            a0 = fmaf(s1.x, v1.x, a0); a1 = fmaf(s1.y, v1.y, a1);
            a0 = fmaf(s1.z, v1.z, a0); a1 = fmaf(s1.w, v1.w, a1);
            a0 = fmaf(s2.x, v2.x, a0); a1 = fmaf(s2.y, v2.y, a1);
            a0 = fmaf(s2.z, v2.z, a0); a1 = fmaf(s2.w, v2.w, a1);
            a0 = fmaf(s3.x, v3.x, a0); a1 = fmaf(s3.y, v3.y, a1);
            a0 = fmaf(s3.z, v3.z, a0); a1 = fmaf(s3.w, v3.w, a1);
            float acc = a0 + a1;
            float mx = acc;
            mx = fmaxf(mx, __shfl_xor_sync(gmask, mx, 8));
            mx = fmaxf(mx, __shfl_xor_sync(gmask, mx, 4));
            mx = fmaxf(mx, __shfl_xor_sync(gmask, mx, 2));
            mx = fmaxf(mx, __shfl_xor_sync(gmask, mx, 1));
            float ex = __expf(acc - mx);
            float sum = ex;
            sum += __shfl_xor_sync(gmask, sum, 8);
            sum += __shfl_xor_sync(gmask, sum, 4);
            sum += __shfl_xor_sync(gmask, sum, 2);
            sum += __shfl_xor_sync(gmask, sum, 1);
            Pw[s * 16 + d] = ex / sum;
        }
    }
    __syncthreads();

    // ---- stage C: layer-2 projections, element-blocked ----
    {
        int e  = ln & 7;
        int oq = ln >> 3;
        float* Pe = smem + e * WSM;
        for (int qb = w; qb < 294; qb += ELEMS) {
            int t = qb * 4 + oq;
            int s = t / 24;
            int rem = t - s * 24;
            int m = rem >> 3;
            int o = rem & 7;
            float a[16];
            const float4* pr = (const float4*)(Pe + s * 16);
            ((float4*)a)[0] = pr[0];
            ((float4*)a)[1] = pr[1];
            ((float4*)a)[2] = pr[2];
            ((float4*)a)[3] = pr[3];
            const float4* w4 = (const float4*)(d_W2 + t * 16);
            float acc = dot16(a, w4, 0.f);
            Pe[784 + m * 392 + s * 8 + o] = acc;
        }
    }
    __syncthreads();

    // ---- stage D1: S2[d][e] (8x8), warp=element ----
    {
        float* Q = Pw + 784;
        float* K = Pw + 1176;
        float* S = Pw + 3136;
        for (int idx = ln; idx < 64; idx += 32) {
            int d = idx >> 3, e = idx & 7;
            float acc = 0.f;
            for (int s = 0; s < 49; s++) acc = fmaf(Q[s * 8 + d], K[s * 8 + e], acc);
            S[idx] = acc * (1.0f / 7.0f);
        }
    }
    __syncwarp();

    // ---- stage D2: tok3[s,d] = softmax_d(sum_e S2[d,e]*V2[s,e]) ----
    {
        float* V = Pw + 1568;
        float* S = Pw + 3136;
        int d  = ln & 7;
        int sg = ln >> 3;
        unsigned gmask = 0xFFu << (sg * 8);
        float4 s0 = *(const float4*)&S[d * 8];
        float4 s1 = *(const float4*)&S[d * 8 + 4];
        for (int s = sg; s < 49; s += 4) {
            float4 v0 = *(const float4*)&V[s * 8];
            float4 v1 = *(const float4*)&V[s * 8 + 4];
            float a0 = s0.x * v0.x, a1 = s0.y * v0.y;
            a0 = fmaf(s0.z, v0.z, a0); a1 = fmaf(s0.w, v0.w, a1);
            a0 = fmaf(s1.x, v1.x, a0); a1 = fmaf(s1.y, v1.y, a1);
            a0 = fmaf(s1.z, v1.z, a0); a1 = fmaf(s1.w, v1.w, a1);
            float acc = a0 + a1;
            float mx = acc;
            mx = fmaxf(mx, __shfl_xor_sync(gmask, mx, 4));
            mx = fmaxf(mx, __shfl_xor_sync(gmask, mx, 2));
            mx = fmaxf(mx, __shfl_xor_sync(gmask, mx, 1));
            float ex = __expf(acc - mx);
            float sum = ex;
            sum += __shfl_xor_sync(gmask, sum, 4);
            sum += __shfl_xor_sync(gmask, sum, 2);
            sum += __shfl_xor_sync(gmask, sum, 1);
            Pw[s * 8 + d] = ex / sum;
        }
    }
    __syncwarp();

    // ---- stage E: fc1 (392->16) + relu, repacked weights, warp=element ----
    {
        float* H = Pw + 3392;
        int o  = ln & 15;
        int hh = ln >> 4;
        const float4* wf = (const float4*)d_FC1;
        const float4* f4 = (const float4*)Pw;
        float a0 = 0.f, a1 = 0.f, a2 = 0.f, a3 = 0.f;
        for (int k = 0; k < 49; k++) {
            int jc = hh * 49 + k;
            float4 wv = wf[jc * 16 + o];
            float4 fv = f4[jc];
            a0 = fmaf(wv.x, fv.x, a0);
            a1 = fmaf(wv.y, fv.y, a1);
            a2 = fmaf(wv.z, fv.z, a2);
            a3 = fmaf(wv.w, fv.w, a3);
        }
        float acc = (a0 + a1) + (a2 + a3);
        acc += __shfl_xor_sync(0xFFFFFFFFu, acc, 16);
        if (hh == 0) H[o] = fmaxf(acc + fc1b[o], 0.f);
    }
    __syncwarp();

    // ---- fc2 (16 -> 10) + softmax(10) ----
    {
        float* H = Pw + 3392;
        float logit = -1e30f;
        if (ln < 10) {
            const float* wr = fc2w + ln * 16;
            float acc = fc2b[ln];
#pragma unroll
            for (int i = 0; i < 16; i++) acc = fmaf(wr[i], H[i], acc);
            logit = acc;
        }
        float mx = logit;
#pragma unroll
        for (int off = 16; off >= 1; off >>= 1)
            mx = fmaxf(mx, __shfl_xor_sync(0xFFFFFFFFu, mx, off));
        float ex = (ln < 10) ? __expf(logit - mx) : 0.f;
        float sum = ex;
#pragma unroll
        for (int off = 16; off >= 1; off >>= 1)
            sum += __shfl_xor_sync(0xFFFFFFFFu, sum, off);
        if (ln < 10) out[(size_t)(bElem + w) * 10 + ln] = ex / sum;
    }
}

extern "C" void kernel_launch(void* const* d_in, const int* in_sizes, int n_in,
                              void* d_out, int out_size) {
    const float* x    = (const float*)d_in[0];
    const float* pos  = (const float*)d_in[1];
    const float* WQ1  = (const float*)d_in[2];
    const float* WK1  = (const float*)d_in[3];
    const float* WV1  = (const float*)d_in[4];
    const float* WQ2  = (const float*)d_in[5];
    const float* WK2  = (const float*)d_in[6];
    const float* WV2  = (const float*)d_in[7];
    const float* fc1w = (const float*)d_in[8];
    const float* fc1b = (const float*)d_in[9];
    const float* fc2w = (const float*)d_in[10];
    const float* fc2b = (const float*)d_in[11];
    float* out = (float*)d_out;

    prep_kernel<<<39, 256>>>(pos, WQ1, WK1, WV1, WQ2, WK2, WV2, fc1w);

    const int smem_bytes = ELEMS * WSM * (int)sizeof(float);   // 109,696 B
    cudaFuncSetAttribute(vit_kernel, cudaFuncAttributeMaxDynamicSharedMemorySize, smem_bytes);
    vit_kernel<<<16384 / ELEMS, ELEMS * 32, smem_bytes>>>(x, fc1b, fc2w, fc2b, out);
}